// round 1
// baseline (speedup 1.0000x reference)
#include <cuda_runtime.h>

// SpikingLayer: input (B*T, C,H,W) = (16*128, 32,32,32) f32.
// Per (b, feat) sequence over T=128:
//   state = max(syn_t + state - act, -1)
//   act   = state > 0 ? floorf(state) : 0
// Output act in same (B*T, feat) layout.
//
// Pure HBM-streaming: 256MB in + 256MB out. One thread per 4 features
// (float4), coalesced across the warp at each time step, unrolled x4 with
// front-batched loads for MLP. Streaming cache hints (no reuse).

#define T_STEPS 128
#define FEAT    32768            // 32*32*32
#define F4      (FEAT / 4)       // 8192 float4 per time step
#define BATCH   16

__global__ __launch_bounds__(256, 4)
void spiking_layer_kernel(const float4* __restrict__ x, float4* __restrict__ out) {
    const unsigned tid = blockIdx.x * blockDim.x + threadIdx.x;  // 0 .. 131071
    const unsigned b = tid >> 13;        // / 8192
    const unsigned f = tid & (F4 - 1);   // % 8192

    const size_t base = (size_t)b * T_STEPS * F4 + f;
    const float4* __restrict__ in = x + base;
    float4* __restrict__ o = out + base;

    float sx = 0.f, sy = 0.f, sz = 0.f, sw = 0.f;   // membrane state
    float ax = 0.f, ay = 0.f, az = 0.f, aw = 0.f;   // last activation

    #pragma unroll 1
    for (int t = 0; t < T_STEPS; t += 4) {
        // Front-batch 4 independent streaming loads (MLP = 4)
        float4 v0 = __ldcs(in + (size_t)(t + 0) * F4);
        float4 v1 = __ldcs(in + (size_t)(t + 1) * F4);
        float4 v2 = __ldcs(in + (size_t)(t + 2) * F4);
        float4 v3 = __ldcs(in + (size_t)(t + 3) * F4);

        #define STEP(v)                                                   \
            sx = fmaxf(v.x + sx - ax, -1.0f);                             \
            sy = fmaxf(v.y + sy - ay, -1.0f);                             \
            sz = fmaxf(v.z + sz - az, -1.0f);                             \
            sw = fmaxf(v.w + sw - aw, -1.0f);                             \
            ax = (sx > 0.f) ? floorf(sx) : 0.f;                           \
            ay = (sy > 0.f) ? floorf(sy) : 0.f;                           \
            az = (sz > 0.f) ? floorf(sz) : 0.f;                           \
            aw = (sw > 0.f) ? floorf(sw) : 0.f;

        STEP(v0); __stcs(o + (size_t)(t + 0) * F4, make_float4(ax, ay, az, aw));
        STEP(v1); __stcs(o + (size_t)(t + 1) * F4, make_float4(ax, ay, az, aw));
        STEP(v2); __stcs(o + (size_t)(t + 2) * F4, make_float4(ax, ay, az, aw));
        STEP(v3); __stcs(o + (size_t)(t + 3) * F4, make_float4(ax, ay, az, aw));
        #undef STEP
    }
}

extern "C" void kernel_launch(void* const* d_in, const int* in_sizes, int n_in,
                              void* d_out, int out_size) {
    const float4* x = (const float4*)d_in[0];
    float4* o = (float4*)d_out;
    const int total_threads = BATCH * F4;          // 131072
    spiking_layer_kernel<<<total_threads / 256, 256>>>(x, o);
}

// round 2
// speedup vs baseline: 1.0201x; 1.0201x over previous
#include <cuda_runtime.h>

// SpikingLayer: input (B*T, 32*32*32) f32, B=16, T=128.
// Per (b, feat): state = max(syn_t + state - act, -1); act = state>0 ? floor(state) : 0.
// Pure HBM stream (256MB in + 256MB out). One thread per float4 column.
// R1 changes: software-pipelined loads (prefetch t+4 chunk while computing t)
// to keep loads in flight through compute/store phases, and 1024 CTAs x 128
// threads for finer SM load balance (6.92 CTAs/SM vs 3.46).

#define T_STEPS 128
#define FEAT    32768            // 32*32*32
#define F4      (FEAT / 4)       // 8192 float4 per time step
#define BATCH   16

__global__ __launch_bounds__(128, 8)
void spiking_layer_kernel(const float4* __restrict__ x, float4* __restrict__ out) {
    const unsigned tid = blockIdx.x * blockDim.x + threadIdx.x;  // 0 .. 131071
    const unsigned b = tid >> 13;        // / 8192
    const unsigned f = tid & (F4 - 1);   // % 8192

    const size_t base = (size_t)b * T_STEPS * F4 + f;
    const float4* __restrict__ in = x + base;
    float4* __restrict__ o = out + base;

    float sx = 0.f, sy = 0.f, sz = 0.f, sw = 0.f;   // membrane state
    float ax = 0.f, ay = 0.f, az = 0.f, aw = 0.f;   // last activation

    #define STEP_STORE(v, t_idx)                                          \
        sx = fmaxf(v.x + sx - ax, -1.0f);                                 \
        sy = fmaxf(v.y + sy - ay, -1.0f);                                 \
        sz = fmaxf(v.z + sz - az, -1.0f);                                 \
        sw = fmaxf(v.w + sw - aw, -1.0f);                                 \
        ax = (sx > 0.f) ? floorf(sx) : 0.f;                               \
        ay = (sy > 0.f) ? floorf(sy) : 0.f;                               \
        az = (sz > 0.f) ? floorf(sz) : 0.f;                               \
        aw = (sw > 0.f) ? floorf(sw) : 0.f;                               \
        __stcs(o + (size_t)(t_idx) * F4, make_float4(ax, ay, az, aw));

    // Prologue: load chunk 0
    float4 c0 = __ldcs(in + 0 * (size_t)F4);
    float4 c1 = __ldcs(in + 1 * (size_t)F4);
    float4 c2 = __ldcs(in + 2 * (size_t)F4);
    float4 c3 = __ldcs(in + 3 * (size_t)F4);

    #pragma unroll 1
    for (int t = 0; t < T_STEPS - 4; t += 4) {
        // Prefetch next chunk before touching current one (keeps 8 loads in flight)
        float4 n0 = __ldcs(in + (size_t)(t + 4) * F4);
        float4 n1 = __ldcs(in + (size_t)(t + 5) * F4);
        float4 n2 = __ldcs(in + (size_t)(t + 6) * F4);
        float4 n3 = __ldcs(in + (size_t)(t + 7) * F4);

        STEP_STORE(c0, t + 0);
        STEP_STORE(c1, t + 1);
        STEP_STORE(c2, t + 2);
        STEP_STORE(c3, t + 3);

        c0 = n0; c1 = n1; c2 = n2; c3 = n3;
    }

    // Epilogue: last chunk (t = 124..127)
    STEP_STORE(c0, T_STEPS - 4);
    STEP_STORE(c1, T_STEPS - 3);
    STEP_STORE(c2, T_STEPS - 2);
    STEP_STORE(c3, T_STEPS - 1);

    #undef STEP_STORE
}

extern "C" void kernel_launch(void* const* d_in, const int* in_sizes, int n_in,
                              void* d_out, int out_size) {
    const float4* x = (const float4*)d_in[0];
    float4* o = (float4*)d_out;
    const int total_threads = BATCH * F4;          // 131072
    spiking_layer_kernel<<<total_threads / 128, 128>>>(x, o);
}

// round 3
// speedup vs baseline: 1.0317x; 1.0114x over previous
#include <cuda_runtime.h>

// SpikingLayer: input (B*T, 32*32*32) f32, B=16, T=128.
// Per (b, feat): state = max(syn_t + state - act, -1); act = state>0 ? floor(state) : 0.
// Pure HBM stream (256MB in + 256MB out) -> near LTS/DRAM cap (~6.5 TB/s achieved).
// R2: max-occupancy variant. 2-step pipeline chunk keeps live regs ~30 so we can
// run __launch_bounds__(128,16) = 2048 threads/SM (100% occ), doubling chip-wide
// outstanding loads vs R1's 50% cap. Tests whether DRAM has residual headroom.

#define T_STEPS 128
#define FEAT    32768            // 32*32*32
#define F4      (FEAT / 4)       // 8192 float4 per time step
#define BATCH   16

__global__ __launch_bounds__(128, 16)
void spiking_layer_kernel(const float4* __restrict__ x, float4* __restrict__ out) {
    const unsigned tid = blockIdx.x * blockDim.x + threadIdx.x;  // 0 .. 131071
    const unsigned b = tid >> 13;        // / 8192
    const unsigned f = tid & (F4 - 1);   // % 8192

    const size_t base = (size_t)b * T_STEPS * F4 + f;
    const float4* __restrict__ in = x + base;
    float4* __restrict__ o = out + base;

    float sx = 0.f, sy = 0.f, sz = 0.f, sw = 0.f;   // membrane state
    float ax = 0.f, ay = 0.f, az = 0.f, aw = 0.f;   // last activation

    #define STEP_STORE(v, t_idx)                                          \
        sx = fmaxf(v.x + sx - ax, -1.0f);                                 \
        sy = fmaxf(v.y + sy - ay, -1.0f);                                 \
        sz = fmaxf(v.z + sz - az, -1.0f);                                 \
        sw = fmaxf(v.w + sw - aw, -1.0f);                                 \
        ax = (sx > 0.f) ? floorf(sx) : 0.f;                               \
        ay = (sy > 0.f) ? floorf(sy) : 0.f;                               \
        az = (sz > 0.f) ? floorf(sz) : 0.f;                               \
        aw = (sw > 0.f) ? floorf(sw) : 0.f;                               \
        __stcs(o + (size_t)(t_idx) * F4, make_float4(ax, ay, az, aw));

    // Prologue: chunk 0 (2 steps)
    float4 c0 = __ldcs(in + 0 * (size_t)F4);
    float4 c1 = __ldcs(in + 1 * (size_t)F4);

    #pragma unroll 1
    for (int t = 0; t < T_STEPS - 2; t += 2) {
        float4 n0 = __ldcs(in + (size_t)(t + 2) * F4);
        float4 n1 = __ldcs(in + (size_t)(t + 3) * F4);

        STEP_STORE(c0, t + 0);
        STEP_STORE(c1, t + 1);

        c0 = n0; c1 = n1;
    }

    STEP_STORE(c0, T_STEPS - 2);
    STEP_STORE(c1, T_STEPS - 1);

    #undef STEP_STORE
}

extern "C" void kernel_launch(void* const* d_in, const int* in_sizes, int n_in,
                              void* d_out, int out_size) {
    const float4* x = (const float4*)d_in[0];
    float4* o = (float4*)d_out;
    const int total_threads = BATCH * F4;          // 131072
    spiking_layer_kernel<<<total_threads / 128, 128>>>(x, o);
}